// round 9
// baseline (speedup 1.0000x reference)
#include <cuda_runtime.h>
#include <cuda_fp16.h>

#define B      64
#define TAPE   262144
#define OUT    65536
#define FANIN  16

// Scratch (allocation-free rule: __device__ globals)
__device__ __half g_tape_T[(size_t)TAPE * B];  // 32 MB: tape^T in fp16 [TAPE, B]
__device__ int    g_is64;                      // 1 if index arrays are int64

// ---------------------------------------------------------------------------
// K1: single pass over tape [B, TAPE], 128 cols per block, 256 threads:
//   (a) out = tape              (8 independent float4 ldcs -> stcs, MLP=8)
//   (b) g_tape_T = (half)tape^T (16B stores, default policy -> L2-resident)
//   (c) block 0 publishes index dtype (int64 high words all zero)
// ---------------------------------------------------------------------------
__global__ void __launch_bounds__(256)
transpose_copy_probe_kernel(const float* __restrict__ tape,
                            float* __restrict__ out,
                            const int* __restrict__ in_idx_w) {
    __shared__ float s[2][64][65];   // [tile][col][batch]
    const int t  = threadIdx.x;      // 0..255
    const int bk = blockIdx.x;       // 0..2047
    const int t0 = bk * 128;         // tape-col base (2 tiles of 64)

    // Phase A: 8 independent float4 loads, then stores + smem staging
    const int q = t & 15;            // col quad within tile
    const int b = t >> 4;            // 0..15 (batch base)
    float4 v[8];
    size_t off[8];
    #pragma unroll
    for (int u = 0; u < 8; u++) {
        const int tile  = u & 1;
        const int batch = b + 16 * (u >> 1);     // 0..63
        off[u] = (size_t)batch * TAPE + t0 + tile * 64 + 4 * q;
        v[u] = __ldcs((const float4*)(tape + off[u]));
    }
    #pragma unroll
    for (int u = 0; u < 8; u++) {
        __stcs((float4*)(out + off[u]), v[u]);
        const int tile  = u & 1;
        const int batch = b + 16 * (u >> 1);
        s[tile][4 * q + 0][batch] = v[u].x;
        s[tile][4 * q + 1][batch] = v[u].y;
        s[tile][4 * q + 2][batch] = v[u].z;
        s[tile][4 * q + 3][batch] = v[u].w;
    }

    // Dtype probe (block 0): int64 => high words of small indices all zero
    if (bk == 0 && t < 32) {
        const bool ok = (in_idx_w[2 * t + 1] == 0) &&
                        (in_idx_w[2 * (t + 32) + 1] == 0);
        const unsigned m = __ballot_sync(0xffffffffu, ok);
        if (t == 0) g_is64 = (m == 0xffffffffu) ? 1 : 0;
    }
    __syncthreads();

    // Phase B: fp16 convert + write tape_T (4 x 16B stores per thread)
    #pragma unroll
    for (int u2 = 0; u2 < 4; u2++) {
        const int idx  = t + 256 * u2;   // 0..1023
        const int row  = idx >> 3;       // 0..127 (col within block)
        const int g    = idx & 7;        // batch octet
        const int tile = row >> 6;
        const int c    = row & 63;
        __half2 h[4];
        #pragma unroll
        for (int k = 0; k < 4; k++)
            h[k] = __floats2half2_rn(s[tile][c][8 * g + 2 * k],
                                     s[tile][c][8 * g + 2 * k + 1]);
        *(uint4*)(g_tape_T + (size_t)(t0 + row) * B + 8 * g) = *(uint4*)h;
    }
}

// ---------------------------------------------------------------------------
// K2: fused gather + weighted-sum + activation + scatter.
// Block = 16 warps x 4 outputs = 64 outputs; lane l holds batches (2l, 2l+1).
// 4 independent half2 gather streams per warp from L2-resident fp16 tape_T.
// Scatter always goes through s_oi (real output_indices): coalesced when
// arange, still correct for arbitrary indices. No probe, no fallback kernel.
// ---------------------------------------------------------------------------
__global__ void __launch_bounds__(512)
gather_scatter_kernel(const float* __restrict__ weights,
                      const float* __restrict__ bias,
                      const void*  __restrict__ input_indices,
                      const void*  __restrict__ output_indices,
                      const void*  __restrict__ act_ids,
                      float* __restrict__ out) {
    __shared__ int   s_idx[1024];    // 64 outputs x 16 fanin
    __shared__ float s_w[1024];
    __shared__ float s_bias[64];
    __shared__ int   s_act[64];
    __shared__ int   s_oi[64];
    __shared__ float sx[64][65];     // [output][batch]; reads conflict-free

    const int t    = threadIdx.x;    // 0..511
    const int o0   = blockIdx.x * 64;
    const int is64 = g_is64;

    #pragma unroll
    for (int r = 0; r < 2; r++) {
        const int i = t + 512 * r;
        s_idx[i] = is64 ? (int)((const long long*)input_indices)[(size_t)o0 * FANIN + i]
                        : ((const int*)input_indices)[(size_t)o0 * FANIN + i];
        s_w[i] = weights[(size_t)o0 * FANIN + i];
    }
    if (t < 64) {
        s_bias[t] = bias[o0 + t];
        s_act[t]  = is64 ? (int)((const long long*)act_ids)[o0 + t]
                         : ((const int*)act_ids)[o0 + t];
        s_oi[t]   = is64 ? (int)((const long long*)output_indices)[o0 + t]
                         : ((const int*)output_indices)[o0 + t];
    }
    __syncthreads();

    const int warp = t >> 5;         // 0..15
    const int lane = t & 31;
    const int ob   = 4 * warp;       // local output base

    float2 acc[4];
    #pragma unroll
    for (int r = 0; r < 4; r++)
        acc[r] = make_float2(s_bias[ob + r], s_bias[ob + r]);

    #pragma unroll
    for (int f = 0; f < FANIN; f++) {
        #pragma unroll
        for (int r = 0; r < 4; r++) {
            const int   idx = s_idx[(ob + r) * FANIN + f];
            const float w   = s_w[(ob + r) * FANIN + f];
            const float2 vv = __half22float2(
                ((const __half2*)(g_tape_T + (size_t)idx * B))[lane]);
            acc[r].x = fmaf(w, vv.x, acc[r].x);
            acc[r].y = fmaf(w, vv.y, acc[r].y);
        }
    }

    #pragma unroll
    for (int r = 0; r < 4; r++) {
        const int a = s_act[ob + r];
        if (a == 0) {
            acc[r].x = fmaxf(acc[r].x, 0.f);
            acc[r].y = fmaxf(acc[r].y, 0.f);
        } else if (a == 1) {
            acc[r].x = 1.f / (1.f + __expf(-acc[r].x));
            acc[r].y = 1.f / (1.f + __expf(-acc[r].y));
        } else {
            acc[r].x = tanhf(acc[r].x);
            acc[r].y = tanhf(acc[r].y);
        }
        sx[ob + r][2 * lane]     = acc[r].x;
        sx[ob + r][2 * lane + 1] = acc[r].y;
    }
    __syncthreads();

    // Scatter: thread t -> output column s_oi[t&63], 8 batches (t>>6 + 8r).
    // 64 consecutive threads hit 64 consecutive columns when arange (256B).
    const int j  = t & 63;
    const int b0 = t >> 6;           // 0..7
    const int oi = s_oi[j];
    #pragma unroll
    for (int r = 0; r < 8; r++)
        __stcs(out + (size_t)(b0 + 8 * r) * TAPE + oi, sx[j][b0 + 8 * r]);
}

// ---------------------------------------------------------------------------
extern "C" void kernel_launch(void* const* d_in, const int* in_sizes, int n_in,
                              void* d_out, int out_size) {
    const float* tape           = (const float*)d_in[0];
    const float* weights        = (const float*)d_in[1];
    const float* bias           = (const float*)d_in[2];
    const void*  input_indices  = d_in[3];
    const void*  output_indices = d_in[4];
    const void*  act_ids        = d_in[5];
    float* out = (float*)d_out;

    // K1: read tape once -> copy to out + fp16 transpose to tape_T (+ dtype)
    transpose_copy_probe_kernel<<<TAPE / 128, 256>>>(
        tape, out, (const int*)input_indices);

    // K2: gather + dot + activation + scatter through real output_indices
    gather_scatter_kernel<<<OUT / 64, 512>>>(weights, bias, input_indices,
                                             output_indices, act_ids, out);
}

// round 10
// speedup vs baseline: 1.0136x; 1.0136x over previous
#include <cuda_runtime.h>
#include <cuda_fp16.h>

#define B      64
#define TAPE   262144
#define OUT    65536
#define FANIN  16

// Scratch (allocation-free rule: __device__ globals)
__device__ __half g_tape_T[(size_t)TAPE * B];  // 32 MB: tape^T in fp16 [TAPE, B]
__device__ int    g_is64;                      // 1 if index arrays are int64

// ---------------------------------------------------------------------------
// K1: single pass over tape [B, TAPE], 128 cols per block, 256 threads:
//   (a) out = tape              (8 independent float4 ldcs -> stcs, MLP=8)
//   (b) g_tape_T = (half)tape^T (16B stores, default policy -> L2-resident)
//   (c) block 0 publishes index dtype (int64 high words all zero)
// ---------------------------------------------------------------------------
__global__ void __launch_bounds__(256)
transpose_copy_probe_kernel(const float* __restrict__ tape,
                            float* __restrict__ out,
                            const int* __restrict__ in_idx_w) {
    __shared__ float s[2][64][65];   // [tile][col][batch]
    const int t  = threadIdx.x;      // 0..255
    const int bk = blockIdx.x;       // 0..2047
    const int t0 = bk * 128;         // tape-col base (2 tiles of 64)

    // Phase A: 8 independent float4 loads, then stores + smem staging
    const int q = t & 15;            // col quad within tile
    const int b = t >> 4;            // 0..15 (batch base)
    float4 v[8];
    size_t off[8];
    #pragma unroll
    for (int u = 0; u < 8; u++) {
        const int tile  = u & 1;
        const int batch = b + 16 * (u >> 1);     // 0..63
        off[u] = (size_t)batch * TAPE + t0 + tile * 64 + 4 * q;
        v[u] = __ldcs((const float4*)(tape + off[u]));
    }
    #pragma unroll
    for (int u = 0; u < 8; u++) {
        __stcs((float4*)(out + off[u]), v[u]);
        const int tile  = u & 1;
        const int batch = b + 16 * (u >> 1);
        s[tile][4 * q + 0][batch] = v[u].x;
        s[tile][4 * q + 1][batch] = v[u].y;
        s[tile][4 * q + 2][batch] = v[u].z;
        s[tile][4 * q + 3][batch] = v[u].w;
    }

    // Dtype probe (block 0): int64 => high words of small indices all zero
    if (bk == 0 && t < 32) {
        const bool ok = (in_idx_w[2 * t + 1] == 0) &&
                        (in_idx_w[2 * (t + 32) + 1] == 0);
        const unsigned m = __ballot_sync(0xffffffffu, ok);
        if (t == 0) g_is64 = (m == 0xffffffffu) ? 1 : 0;
    }
    __syncthreads();

    // Phase B: fp16 convert + write tape_T (4 x 16B stores per thread)
    #pragma unroll
    for (int u2 = 0; u2 < 4; u2++) {
        const int idx  = t + 256 * u2;   // 0..1023
        const int row  = idx >> 3;       // 0..127 (col within block)
        const int g    = idx & 7;        // batch octet
        const int tile = row >> 6;
        const int c    = row & 63;
        __half2 h[4];
        #pragma unroll
        for (int k = 0; k < 4; k++)
            h[k] = __floats2half2_rn(s[tile][c][8 * g + 2 * k],
                                     s[tile][c][8 * g + 2 * k + 1]);
        *(uint4*)(g_tape_T + (size_t)(t0 + row) * B + 8 * g) = *(uint4*)h;
    }
}

// ---------------------------------------------------------------------------
// K2: fused gather + weighted-sum + activation + scatter.
// Block = 16 warps x 2 outputs = 32 outputs (R8 shape: high occupancy won
// over wider ILP in R9's profile). Lane l holds batches (2l, 2l+1); 2
// independent half2 gather streams per warp from L2-resident fp16 tape_T.
// Scatter always goes through s_oi (real output_indices): coalesced when
// arange, still correct for arbitrary indices. No probe, no fallback kernel.
// ---------------------------------------------------------------------------
__global__ void __launch_bounds__(512)
gather_scatter_kernel(const float* __restrict__ weights,
                      const float* __restrict__ bias,
                      const void*  __restrict__ input_indices,
                      const void*  __restrict__ output_indices,
                      const void*  __restrict__ act_ids,
                      float* __restrict__ out) {
    __shared__ int   s_idx[512];     // 32 outputs x 16 fanin
    __shared__ float s_w[512];
    __shared__ float s_bias[32];
    __shared__ int   s_act[32];
    __shared__ int   s_oi[32];
    __shared__ float sx[32][66];     // [output][batch]

    const int t    = threadIdx.x;    // 0..511
    const int o0   = blockIdx.x * 32;
    const int is64 = g_is64;

    s_idx[t] = is64 ? (int)((const long long*)input_indices)[(size_t)o0 * FANIN + t]
                    : ((const int*)input_indices)[(size_t)o0 * FANIN + t];
    s_w[t] = weights[(size_t)o0 * FANIN + t];
    if (t < 32) {
        s_bias[t] = bias[o0 + t];
        s_act[t]  = is64 ? (int)((const long long*)act_ids)[o0 + t]
                         : ((const int*)act_ids)[o0 + t];
        s_oi[t]   = is64 ? (int)((const long long*)output_indices)[o0 + t]
                         : ((const int*)output_indices)[o0 + t];
    }
    __syncthreads();

    const int warp = t >> 5;         // 0..15
    const int lane = t & 31;
    const int oA = 2 * warp;
    const int oB = 2 * warp + 1;

    float2 accA = make_float2(s_bias[oA], s_bias[oA]);
    float2 accB = make_float2(s_bias[oB], s_bias[oB]);

    #pragma unroll
    for (int f = 0; f < FANIN; f++) {
        const int   iA = s_idx[oA * FANIN + f];
        const int   iB = s_idx[oB * FANIN + f];
        const float wA = s_w[oA * FANIN + f];
        const float wB = s_w[oB * FANIN + f];
        const float2 vA = __half22float2(((const __half2*)(g_tape_T + (size_t)iA * B))[lane]);
        const float2 vB = __half22float2(((const __half2*)(g_tape_T + (size_t)iB * B))[lane]);
        accA.x = fmaf(wA, vA.x, accA.x);
        accA.y = fmaf(wA, vA.y, accA.y);
        accB.x = fmaf(wB, vB.x, accB.x);
        accB.y = fmaf(wB, vB.y, accB.y);
    }

    #pragma unroll
    for (int r = 0; r < 2; r++) {
        float2& acc = r ? accB : accA;
        const int a = s_act[r ? oB : oA];
        if (a == 0) {
            acc.x = fmaxf(acc.x, 0.f);
            acc.y = fmaxf(acc.y, 0.f);
        } else if (a == 1) {
            acc.x = 1.f / (1.f + __expf(-acc.x));
            acc.y = 1.f / (1.f + __expf(-acc.y));
        } else {
            acc.x = tanhf(acc.x);
            acc.y = tanhf(acc.y);
        }
    }

    sx[oA][2 * lane] = accA.x; sx[oA][2 * lane + 1] = accA.y;
    sx[oB][2 * lane] = accB.x; sx[oB][2 * lane + 1] = accB.y;
    __syncthreads();

    // Scatter: thread t -> output column s_oi[t&31], 4 batches (t>>5 + 16r).
    // 32 consecutive threads -> 128B contiguous per batch row when arange.
    const int j  = t & 31;
    const int b0 = t >> 5;           // 0..15
    const int oi = s_oi[j];
    #pragma unroll
    for (int r = 0; r < 4; r++)
        __stcs(out + (size_t)(b0 + 16 * r) * TAPE + oi, sx[j][b0 + 16 * r]);
}

// ---------------------------------------------------------------------------
extern "C" void kernel_launch(void* const* d_in, const int* in_sizes, int n_in,
                              void* d_out, int out_size) {
    const float* tape           = (const float*)d_in[0];
    const float* weights        = (const float*)d_in[1];
    const float* bias           = (const float*)d_in[2];
    const void*  input_indices  = d_in[3];
    const void*  output_indices = d_in[4];
    const void*  act_ids        = d_in[5];
    float* out = (float*)d_out;

    // K1: read tape once -> copy to out + fp16 transpose to tape_T (+ dtype)
    transpose_copy_probe_kernel<<<TAPE / 128, 256>>>(
        tape, out, (const int*)input_indices);

    // K2: gather + dot + activation + scatter through real output_indices
    gather_scatter_kernel<<<OUT / 32, 512>>>(weights, bias, input_indices,
                                             output_indices, act_ids, out);
}

// round 11
// speedup vs baseline: 1.0454x; 1.0314x over previous
#include <cuda_runtime.h>
#include <cuda_fp16.h>

#define B      64
#define TAPE   262144
#define OUT    65536
#define FANIN  16

// Scratch (allocation-free rule: __device__ globals)
__device__ __half g_tape_T[(size_t)TAPE * B];  // 32 MB: tape^T in fp16 [TAPE, B]
__device__ int    g_is64;                      // 1 if index arrays are int64

// ---------------------------------------------------------------------------
// K1: single pass over tape [B, TAPE], 128 cols per block, 256 threads:
//   (a) out = tape              (8 independent float4 ldcs -> stcs, MLP=8)
//   (b) g_tape_T = (half)tape^T (16B stores, default policy -> L2-resident)
//   (c) block 0 publishes index dtype (int64 high words all zero)
// Measured ~20.7us for 128MB mandatory DRAM (~6.2TB/s) — near floor.
// ---------------------------------------------------------------------------
__global__ void __launch_bounds__(256)
transpose_copy_probe_kernel(const float* __restrict__ tape,
                            float* __restrict__ out,
                            const int* __restrict__ in_idx_w) {
    __shared__ float s[2][64][65];   // [tile][col][batch]
    const int t  = threadIdx.x;      // 0..255
    const int bk = blockIdx.x;       // 0..2047
    const int t0 = bk * 128;         // tape-col base (2 tiles of 64)

    // Phase A: 8 independent float4 loads, then stores + smem staging
    const int q = t & 15;            // col quad within tile
    const int b = t >> 4;            // 0..15 (batch base)
    float4 v[8];
    size_t off[8];
    #pragma unroll
    for (int u = 0; u < 8; u++) {
        const int tile  = u & 1;
        const int batch = b + 16 * (u >> 1);     // 0..63
        off[u] = (size_t)batch * TAPE + t0 + tile * 64 + 4 * q;
        v[u] = __ldcs((const float4*)(tape + off[u]));
    }
    #pragma unroll
    for (int u = 0; u < 8; u++) {
        __stcs((float4*)(out + off[u]), v[u]);
        const int tile  = u & 1;
        const int batch = b + 16 * (u >> 1);
        s[tile][4 * q + 0][batch] = v[u].x;
        s[tile][4 * q + 1][batch] = v[u].y;
        s[tile][4 * q + 2][batch] = v[u].z;
        s[tile][4 * q + 3][batch] = v[u].w;
    }

    // Dtype probe (block 0): int64 => high words of small indices all zero
    if (bk == 0 && t < 32) {
        const bool ok = (in_idx_w[2 * t + 1] == 0) &&
                        (in_idx_w[2 * (t + 32) + 1] == 0);
        const unsigned m = __ballot_sync(0xffffffffu, ok);
        if (t == 0) g_is64 = (m == 0xffffffffu) ? 1 : 0;
    }
    __syncthreads();

    // Phase B: fp16 convert + write tape_T (4 x 16B stores per thread)
    #pragma unroll
    for (int u2 = 0; u2 < 4; u2++) {
        const int idx  = t + 256 * u2;   // 0..1023
        const int row  = idx >> 3;       // 0..127 (col within block)
        const int g    = idx & 7;        // batch octet
        const int tile = row >> 6;
        const int c    = row & 63;
        __half2 h[4];
        #pragma unroll
        for (int k = 0; k < 4; k++)
            h[k] = __floats2half2_rn(s[tile][c][8 * g + 2 * k],
                                     s[tile][c][8 * g + 2 * k + 1]);
        *(uint4*)(g_tape_T + (size_t)(t0 + row) * B + 8 * g) = *(uint4*)h;
    }
}

// ---------------------------------------------------------------------------
// K2: fused gather + weighted-sum + activation + scatter.
// Block = 16 warps x 2 outputs = 32 outputs. Inner loop per (output, f):
// one LDS.64 of packed (byte_off, weight) + one LDG.32 (half2) + cvt + 2 FFMA.
// __launch_bounds__(512, 4) clamps regs to 32 -> 4 blocks/SM (occ ~100%) to
// hide the 234-cycle L2 latency of the gather stream.
// ---------------------------------------------------------------------------
__global__ void __launch_bounds__(512, 4)
gather_scatter_kernel(const float* __restrict__ weights,
                      const float* __restrict__ bias,
                      const void*  __restrict__ input_indices,
                      const void*  __restrict__ output_indices,
                      const void*  __restrict__ act_ids,
                      float* __restrict__ out) {
    __shared__ int2  s_iw[512];      // 32 outputs x 16 fanin: (byte_off, w bits)
    __shared__ float s_bias[32];
    __shared__ int   s_act[32];
    __shared__ int   s_oi[32];
    __shared__ float sx[32][66];     // [output][batch]

    const int t    = threadIdx.x;    // 0..511
    const int o0   = blockIdx.x * 32;
    const int is64 = g_is64;

    {
        const int idx = is64 ? (int)((const long long*)input_indices)[(size_t)o0 * FANIN + t]
                             : ((const int*)input_indices)[(size_t)o0 * FANIN + t];
        const float w = weights[(size_t)o0 * FANIN + t];
        s_iw[t] = make_int2(idx * (B * 2), __float_as_int(w));  // byte offset into fp16 tape_T
    }
    if (t < 32) {
        s_bias[t] = bias[o0 + t];
        s_act[t]  = is64 ? (int)((const long long*)act_ids)[o0 + t]
                         : ((const int*)act_ids)[o0 + t];
        s_oi[t]   = is64 ? (int)((const long long*)output_indices)[o0 + t]
                         : ((const int*)output_indices)[o0 + t];
    }
    __syncthreads();

    const int warp = t >> 5;         // 0..15
    const int lane = t & 31;
    const int oA = 2 * warp;
    const int oB = 2 * warp + 1;
    const char* tT = (const char*)g_tape_T + lane * 4;  // lane's half2 column

    float2 accA = make_float2(s_bias[oA], s_bias[oA]);
    float2 accB = make_float2(s_bias[oB], s_bias[oB]);

    #pragma unroll
    for (int f = 0; f < FANIN; f++) {
        const int2 iwA = s_iw[oA * FANIN + f];
        const int2 iwB = s_iw[oB * FANIN + f];
        const float2 vA = __half22float2(*(const __half2*)(tT + iwA.x));
        const float2 vB = __half22float2(*(const __half2*)(tT + iwB.x));
        const float wA = __int_as_float(iwA.y);
        const float wB = __int_as_float(iwB.y);
        accA.x = fmaf(wA, vA.x, accA.x);
        accA.y = fmaf(wA, vA.y, accA.y);
        accB.x = fmaf(wB, vB.x, accB.x);
        accB.y = fmaf(wB, vB.y, accB.y);
    }

    #pragma unroll
    for (int r = 0; r < 2; r++) {
        float2& acc = r ? accB : accA;
        const int a = s_act[r ? oB : oA];
        if (a == 0) {
            acc.x = fmaxf(acc.x, 0.f);
            acc.y = fmaxf(acc.y, 0.f);
        } else if (a == 1) {
            acc.x = 1.f / (1.f + __expf(-acc.x));
            acc.y = 1.f / (1.f + __expf(-acc.y));
        } else {
            acc.x = tanhf(acc.x);
            acc.y = tanhf(acc.y);
        }
    }

    sx[oA][2 * lane] = accA.x; sx[oA][2 * lane + 1] = accA.y;
    sx[oB][2 * lane] = accB.x; sx[oB][2 * lane + 1] = accB.y;
    __syncthreads();

    // Scatter: thread t -> output column s_oi[t&31], 4 batches (t>>5 + 16r).
    // 32 consecutive threads -> 128B contiguous per batch row when arange.
    const int j  = t & 31;
    const int b0 = t >> 5;           // 0..15
    const int oi = s_oi[j];
    #pragma unroll
    for (int r = 0; r < 4; r++)
        __stcs(out + (size_t)(b0 + 16 * r) * TAPE + oi, sx[j][b0 + 16 * r]);
}

// ---------------------------------------------------------------------------
extern "C" void kernel_launch(void* const* d_in, const int* in_sizes, int n_in,
                              void* d_out, int out_size) {
    const float* tape           = (const float*)d_in[0];
    const float* weights        = (const float*)d_in[1];
    const float* bias           = (const float*)d_in[2];
    const void*  input_indices  = d_in[3];
    const void*  output_indices = d_in[4];
    const void*  act_ids        = d_in[5];
    float* out = (float*)d_out;

    // K1: read tape once -> copy to out + fp16 transpose to tape_T (+ dtype)
    transpose_copy_probe_kernel<<<TAPE / 128, 256>>>(
        tape, out, (const int*)input_indices);

    // K2: gather + dot + activation + scatter through real output_indices
    gather_scatter_kernel<<<OUT / 32, 512>>>(weights, bias, input_indices,
                                             output_indices, act_ids, out);
}